// round 15
// baseline (speedup 1.0000x reference)
#include <cuda_runtime.h>
#include <cstdint>
#include <math.h>

#define BB 2
#define SS_ 4096
#define DD 768
#define HH 12
#define DK 64
#define MTOT (BB*SS_)   // 8192

// Scratch (allocation-free rule: __device__ globals)
__device__ float g_q[(size_t)BB*HH*SS_*DK];
__device__ float g_k[(size_t)BB*HH*SS_*DK];
__device__ float g_v[(size_t)BB*HH*SS_*DK];
__device__ float g_o[(size_t)BB*HH*SS_*DK];

// ---------------------------------------------------------------------------
// helpers
// ---------------------------------------------------------------------------
__device__ __forceinline__ float to_tf32(float x) {
    uint32_t u;
    asm("cvt.rna.tf32.f32 %0, %1;" : "=r"(u) : "f"(x));
    return __uint_as_float(u);
}

__device__ __forceinline__ void mma_tf32(float* d, const float* a, float b0, float b1) {
    asm volatile(
        "mma.sync.aligned.m16n8k8.row.col.f32.tf32.tf32.f32 "
        "{%0,%1,%2,%3}, {%4,%5,%6,%7}, {%8,%9}, {%0,%1,%2,%3};"
        : "+f"(d[0]), "+f"(d[1]), "+f"(d[2]), "+f"(d[3])
        : "r"(__float_as_uint(a[0])), "r"(__float_as_uint(a[1])),
          "r"(__float_as_uint(a[2])), "r"(__float_as_uint(a[3])),
          "r"(__float_as_uint(b0)),   "r"(__float_as_uint(b1)));
}

__device__ __forceinline__ float4 cvt4(float4 v) {
    v.x = to_tf32(v.x); v.y = to_tf32(v.y);
    v.z = to_tf32(v.z); v.w = to_tf32(v.w);
    return v;
}

// ===========================================================================
// Projection GEMM (tf32 mma.sync), register-prefetch pipeline, K-chunk 32,
// double smem buffer, one barrier per chunk.  (unchanged — 213 us measured)
// ===========================================================================
#define PK 32
#define PAS 36
#define PBS 136
#define PBUF (128*PAS + PK*PBS)
#define PROJ_SMEM (2 * PBUF * 4)

__device__ __forceinline__ void proj_ldg(
    float4* Ar, float4* Br,
    const float* __restrict__ A_base, const float* __restrict__ Wm,
    int m0, int n0, int k0, int t, int mode)
{
    if (mode == 0) {
        #pragma unroll
        for (int i = 0; i < 4; i++) {
            int idx = t + 256 * i;
            int row = idx >> 3, c4 = idx & 7;
            Ar[i] = *(const float4*)(A_base + (size_t)(m0 + row) * DD + k0 + c4 * 4);
        }
    } else {
        const int h = k0 >> 6;
        const int cb = k0 & 63;
        #pragma unroll
        for (int i = 0; i < 4; i++) {
            int idx = t + 256 * i;
            int row = idx >> 3, c4 = idx & 7;
            int m = m0 + row;
            int bb = m >> 12, ss = m & 4095;
            Ar[i] = *(const float4*)(A_base + (((size_t)bb * HH + h) * SS_ + ss) * DK + cb + c4 * 4);
        }
    }
    #pragma unroll
    for (int i = 0; i < 4; i++) {
        int idx = t + 256 * i;
        int k = idx >> 5, n4 = idx & 31;
        Br[i] = *(const float4*)(Wm + (size_t)(k0 + k) * DD + n0 + n4 * 4);
    }
}

__device__ __forceinline__ void proj_sts(
    float* As, float* Bs, const float4* Ar, const float4* Br, int t)
{
    #pragma unroll
    for (int i = 0; i < 4; i++) {
        int idx = t + 256 * i;
        *(float4*)&As[(idx >> 3) * PAS + (idx & 7) * 4] = cvt4(Ar[i]);
    }
    #pragma unroll
    for (int i = 0; i < 4; i++) {
        int idx = t + 256 * i;
        *(float4*)&Bs[(idx >> 5) * PBS + (idx & 31) * 4] = cvt4(Br[i]);
    }
}

__device__ __forceinline__ void proj_gemm_body(
    const float* __restrict__ A_base,
    const float* __restrict__ Wm, const float* __restrict__ bias,
    float* __restrict__ out, int mode)
{
    extern __shared__ float sm[];

    const int t    = threadIdx.x;
    const int w    = t >> 5;
    const int lane = t & 31;
    const int gid  = lane >> 2;
    const int tig  = lane & 3;
    const int wm   = w & 3;
    const int wn   = w >> 2;
    const int m0   = blockIdx.x * 128;
    const int n0   = blockIdx.y * 128;
    const int m0w  = wm * 32;
    const int n0w  = wn * 64;

    float acc[2][8][4];
    #pragma unroll
    for (int mt = 0; mt < 2; mt++)
        #pragma unroll
        for (int nt = 0; nt < 8; nt++)
            #pragma unroll
            for (int i = 0; i < 4; i++) acc[mt][nt][i] = 0.f;

    float4 Ar[4], Br[4];
    proj_ldg(Ar, Br, A_base, Wm, m0, n0, 0, t, mode);
    proj_sts(sm, sm + 128 * PAS, Ar, Br, t);
    __syncthreads();

    const int NCH = DD / PK;   // 24
    for (int c = 0; c < NCH; c++) {
        const int cur = c & 1;
        float* As = sm + cur * PBUF;
        float* Bs = As + 128 * PAS;

        if (c + 1 < NCH)
            proj_ldg(Ar, Br, A_base, Wm, m0, n0, (c + 1) * PK, t, mode);

        #pragma unroll
        for (int k = 0; k < PK / 8; k++) {
            float af[2][4];
            #pragma unroll
            for (int mt = 0; mt < 2; mt++) {
                int r = m0w + mt * 16;
                af[mt][0] = As[(r + gid)     * PAS + k * 8 + tig];
                af[mt][1] = As[(r + gid + 8) * PAS + k * 8 + tig];
                af[mt][2] = As[(r + gid)     * PAS + k * 8 + tig + 4];
                af[mt][3] = As[(r + gid + 8) * PAS + k * 8 + tig + 4];
            }
            #pragma unroll
            for (int nt = 0; nt < 8; nt++) {
                float b0 = Bs[(k * 8 + tig)     * PBS + n0w + nt * 8 + gid];
                float b1 = Bs[(k * 8 + tig + 4) * PBS + n0w + nt * 8 + gid];
                mma_tf32(acc[0][nt], af[0], b0, b1);
                mma_tf32(acc[1][nt], af[1], b0, b1);
            }
        }

        if (c + 1 < NCH) {
            float* As2 = sm + (cur ^ 1) * PBUF;
            proj_sts(As2, As2 + 128 * PAS, Ar, Br, t);
        }
        __syncthreads();
    }

    #pragma unroll
    for (int mt = 0; mt < 2; mt++) {
        int mrow = m0 + m0w + mt * 16 + gid;
        #pragma unroll
        for (int nt = 0; nt < 8; nt++) {
            int n = n0 + n0w + nt * 8 + tig * 2;
            float b0 = bias[n], b1 = bias[n + 1];
            if (mode == 0) {
                int h = n >> 6, cc = n & 63;
                int bb0 = mrow >> 12, ss0 = mrow & 4095;
                int m8 = mrow + 8;
                int bb1 = m8 >> 12, ss1 = m8 & 4095;
                *(float2*)(out + (((size_t)bb0 * HH + h) * SS_ + ss0) * DK + cc) =
                    make_float2(acc[mt][nt][0] + b0, acc[mt][nt][1] + b1);
                *(float2*)(out + (((size_t)bb1 * HH + h) * SS_ + ss1) * DK + cc) =
                    make_float2(acc[mt][nt][2] + b0, acc[mt][nt][3] + b1);
            } else {
                *(float2*)(out + (size_t)mrow * DD + n) =
                    make_float2(acc[mt][nt][0] + b0, acc[mt][nt][1] + b1);
                *(float2*)(out + (size_t)(mrow + 8) * DD + n) =
                    make_float2(acc[mt][nt][2] + b0, acc[mt][nt][3] + b1);
            }
        }
    }
}

__global__ __launch_bounds__(256, 2) void gemm_qkv_mma(
    const float* __restrict__ X,
    const float* __restrict__ wq, const float* __restrict__ bq,
    const float* __restrict__ wk, const float* __restrict__ bk,
    const float* __restrict__ wv, const float* __restrict__ bv)
{
    const float* Wm; const float* bias; float* out;
    if (blockIdx.z == 0)      { Wm = wq; bias = bq; out = g_q; }
    else if (blockIdx.z == 1) { Wm = wk; bias = bk; out = g_k; }
    else                      { Wm = wv; bias = bv; out = g_v; }
    proj_gemm_body(X, Wm, bias, out, 0);
}

__global__ __launch_bounds__(256, 2) void gemm_out_mma(
    const float* __restrict__ wo, const float* __restrict__ bo,
    float* __restrict__ Y)
{
    proj_gemm_body(g_o, wo, bo, Y, 1);
}

// ---------------------------------------------------------------------------
// Flash attention, mma.sync tf32 (m16n8k8), wide warp tiles + HIGH OCCUPANCY:
// CTA = 128 threads / 4 warps; warp w owns 32 q rows (2 m-tiles of 16).
// TKV = 32 -> smem 70.6 KB -> 3 CTAs/SM (12 warps, 3/SMSP) with regs <= 170
// via __launch_bounds__(128,3).  Same math order as R14 -> bit-identical.
// smem: Q [128][68], K 2x[32][68], V 2x[32][72]
// ---------------------------------------------------------------------------
#define TKV 32
#define QS_STR 68
#define KS_STR 68
#define VS_STR 72
#define KVBUF (TKV*KS_STR + TKV*VS_STR)
#define ATT_SMEM ((128*QS_STR + 2*KVBUF) * 4)   // 70656 B

__device__ __forceinline__ void attn_ldg(
    float4* Kr, float4* Vr,
    const float* __restrict__ Kg, const float* __restrict__ Vg, int kv0, int t)
{
    #pragma unroll
    for (int i = 0; i < 4; i++) {
        int f = t + 128 * i;
        int row = f >> 4, c4 = f & 15;
        Kr[i] = *(const float4*)(Kg + (size_t)(kv0 + row) * DK + c4 * 4);
    }
    #pragma unroll
    for (int i = 0; i < 4; i++) {
        int f = t + 128 * i;
        int row = f >> 4, c4 = f & 15;
        Vr[i] = *(const float4*)(Vg + (size_t)(kv0 + row) * DK + c4 * 4);
    }
}

__device__ __forceinline__ void attn_sts(
    float* Ks, float* Vs, const float4* Kr, const float4* Vr, int t)
{
    #pragma unroll
    for (int i = 0; i < 4; i++) {
        int f = t + 128 * i;
        *(float4*)&Ks[(f >> 4) * KS_STR + (f & 15) * 4] = cvt4(Kr[i]);
    }
    #pragma unroll
    for (int i = 0; i < 4; i++) {
        int f = t + 128 * i;
        *(float4*)&Vs[(f >> 4) * VS_STR + (f & 15) * 4] = cvt4(Vr[i]);
    }
}

__global__ __launch_bounds__(128, 3) void attn_mma()
{
    extern __shared__ float sm[];
    float* Qs  = sm;                       // [128][68]
    float* KV0 = Qs + 128 * QS_STR;        // buffer 0: K[32][68] V[32][72]
    float* KV1 = KV0 + KVBUF;              // buffer 1

    const int t    = threadIdx.x;
    const int w    = t >> 5;               // 0..3
    const int lane = t & 31;
    const int gid  = lane >> 2;
    const int tig  = lane & 3;

    const int q0 = blockIdx.x * 128;
    const int bh = blockIdx.y;

    const float* Qg = g_q + (size_t)bh * SS_ * DK;
    const float* Kg = g_k + (size_t)bh * SS_ * DK;
    const float* Vg = g_v + (size_t)bh * SS_ * DK;
    float*       Og = g_o + (size_t)bh * SS_ * DK;

    // shuffle source lanes for P redistribution (within quad)
    const int s0 = (lane & ~3) | (tig >> 1);
    const int s2 = s0 + 2;
    const bool odd = (tig & 1);

    // ---- stage Q (once): scaled by 1/8, tf32, stride-68 ----
    #pragma unroll
    for (int i = 0; i < 16; i++) {
        int f = t + 128 * i;
        int row = f >> 4, c4 = f & 15;
        float4 v = *(const float4*)(Qg + (size_t)(q0 + row) * DK + c4 * 4);
        v.x *= 0.125f; v.y *= 0.125f; v.z *= 0.125f; v.w *= 0.125f;
        *(float4*)&Qs[row * QS_STR + c4 * 4] = cvt4(v);
    }

    // ---- stage K/V tile 0 into buffer 0 ----
    float4 Kr[4], Vr[4];
    attn_ldg(Kr, Vr, Kg, Vg, 0, t);
    attn_sts(KV0, KV0 + TKV * KS_STR, Kr, Vr, t);
    __syncthreads();

    float oacc[2][8][4];
    #pragma unroll
    for (int mt = 0; mt < 2; mt++)
        #pragma unroll
        for (int n = 0; n < 8; n++)
            #pragma unroll
            for (int i = 0; i < 4; i++) oacc[mt][n][i] = 0.f;
    float ls[2][2] = {{0.f, 0.f}, {0.f, 0.f}};

    const int qrow = w * 32;   // warp's q-row base within tile (2 m-tiles)

    const int NIT = SS_ / TKV;   // 128
    for (int it = 0; it < NIT; it++) {
        float* Ks = (it & 1) ? KV1 : KV0;
        float* Vs = Ks + TKV * KS_STR;
        float* KsN = (it & 1) ? KV0 : KV1;

        // ---- S = Q K^T  (2 m-tiles share every K b-fragment) ----
        float sacc[2][4][4];
        #pragma unroll
        for (int mt = 0; mt < 2; mt++)
            #pragma unroll
            for (int n = 0; n < 4; n++)
                #pragma unroll
                for (int i = 0; i < 4; i++) sacc[mt][n][i] = 0.f;

        #pragma unroll
        for (int k = 0; k < 8; k++) {
            float aq[2][4];
            #pragma unroll
            for (int mt = 0; mt < 2; mt++) {
                int r = qrow + mt * 16;
                aq[mt][0] = Qs[(r + gid)     * QS_STR + k * 8 + tig];
                aq[mt][1] = Qs[(r + gid + 8) * QS_STR + k * 8 + tig];
                aq[mt][2] = Qs[(r + gid)     * QS_STR + k * 8 + tig + 4];
                aq[mt][3] = Qs[(r + gid + 8) * QS_STR + k * 8 + tig + 4];
            }
            #pragma unroll
            for (int nt = 0; nt < 4; nt++) {
                float b0 = Ks[(nt * 8 + gid) * KS_STR + k * 8 + tig];
                float b1 = Ks[(nt * 8 + gid) * KS_STR + k * 8 + tig + 4];
                mma_tf32(sacc[0][nt], aq[0], b0, b1);
                mma_tf32(sacc[1][nt], aq[1], b0, b1);
            }
        }

        // ---- prefetch next K/V tile into registers (hidden behind PV) ----
        if (it + 1 < NIT)
            attn_ldg(Kr, Vr, Kg, Vg, (it + 1) * TKV, t);

        // ---- softmax + PV, interleaved per kv-chunk; P via quad shuffles;
        //      V b-fragments shared by both m-tiles ----
        #pragma unroll
        for (int kc = 0; kc < 4; kc++) {
            float af[2][4];
            #pragma unroll
            for (int mt = 0; mt < 2; mt++) {
                float p0 = __expf(sacc[mt][kc][0]);
                float p1 = __expf(sacc[mt][kc][1]);
                float p2 = __expf(sacc[mt][kc][2]);
                float p3 = __expf(sacc[mt][kc][3]);
                ls[mt][0] += p0 + p1;
                ls[mt][1] += p2 + p3;

                float v00 = __shfl_sync(0xffffffffu, p0, s0);
                float v01 = __shfl_sync(0xffffffffu, p1, s0);
                float v10 = __shfl_sync(0xffffffffu, p2, s0);
                float v11 = __shfl_sync(0xffffffffu, p3, s0);
                float v20 = __shfl_sync(0xffffffffu, p0, s2);
                float v21 = __shfl_sync(0xffffffffu, p1, s2);
                float v30 = __shfl_sync(0xffffffffu, p2, s2);
                float v31 = __shfl_sync(0xffffffffu, p3, s2);

                af[mt][0] = to_tf32(odd ? v01 : v00);
                af[mt][1] = to_tf32(odd ? v11 : v10);
                af[mt][2] = to_tf32(odd ? v21 : v20);
                af[mt][3] = to_tf32(odd ? v31 : v30);
            }

            #pragma unroll
            for (int nt = 0; nt < 8; nt++) {
                float b0 = Vs[(kc * 8 + tig)     * VS_STR + nt * 8 + gid];
                float b1 = Vs[(kc * 8 + tig + 4) * VS_STR + nt * 8 + gid];
                mma_tf32(oacc[0][nt], af[0], b0, b1);
                mma_tf32(oacc[1][nt], af[1], b0, b1);
            }
        }

        // ---- store next tile into the other buffer, one barrier ----
        if (it + 1 < NIT)
            attn_sts(KsN, KsN + TKV * KS_STR, Kr, Vr, t);
        __syncthreads();
    }

    // ---- finalize ----
    #pragma unroll
    for (int mt = 0; mt < 2; mt++) {
        float l0 = ls[mt][0], l1 = ls[mt][1];
        l0 += __shfl_xor_sync(0xffffffffu, l0, 1);
        l0 += __shfl_xor_sync(0xffffffffu, l0, 2);
        l1 += __shfl_xor_sync(0xffffffffu, l1, 1);
        l1 += __shfl_xor_sync(0xffffffffu, l1, 2);
        const float inv0 = 1.f / l0;
        const float inv1 = 1.f / l1;

        const int row0 = q0 + qrow + mt * 16 + gid;
        #pragma unroll
        for (int nt = 0; nt < 8; nt++) {
            *(float2*)(Og + (size_t)row0 * DK + nt * 8 + tig * 2) =
                make_float2(oacc[mt][nt][0] * inv0, oacc[mt][nt][1] * inv0);
            *(float2*)(Og + (size_t)(row0 + 8) * DK + nt * 8 + tig * 2) =
                make_float2(oacc[mt][nt][2] * inv1, oacc[mt][nt][3] * inv1);
        }
    }
}

// ---------------------------------------------------------------------------
extern "C" void kernel_launch(void* const* d_in, const int* in_sizes, int n_in,
                              void* d_out, int out_size)
{
    (void)in_sizes; (void)n_in; (void)out_size;
    const float* x  = (const float*)d_in[0];
    const float* wq = (const float*)d_in[1];
    const float* bq = (const float*)d_in[2];
    const float* wk = (const float*)d_in[3];
    const float* bk = (const float*)d_in[4];
    const float* wv = (const float*)d_in[5];
    const float* bv = (const float*)d_in[6];
    const float* wo = (const float*)d_in[7];
    const float* bo = (const float*)d_in[8];
    float* y = (float*)d_out;

    cudaFuncSetAttribute(attn_mma,     cudaFuncAttributeMaxDynamicSharedMemorySize, ATT_SMEM);
    cudaFuncSetAttribute(gemm_qkv_mma, cudaFuncAttributeMaxDynamicSharedMemorySize, PROJ_SMEM);
    cudaFuncSetAttribute(gemm_out_mma, cudaFuncAttributeMaxDynamicSharedMemorySize, PROJ_SMEM);

    dim3 gq(MTOT / 128, DD / 128, 3);
    gemm_qkv_mma<<<gq, 256, PROJ_SMEM>>>(x, wq, bq, wk, bk, wv, bv);

    dim3 ga(SS_ / 128, BB * HH);
    attn_mma<<<ga, 128, ATT_SMEM>>>();

    dim3 go(MTOT / 128, DD / 128);
    gemm_out_mma<<<go, 256, PROJ_SMEM>>>(wo, bo, y);
}

// round 16
// speedup vs baseline: 1.5170x; 1.5170x over previous
#include <cuda_runtime.h>
#include <cstdint>
#include <math.h>

#define BB 2
#define SS_ 4096
#define DD 768
#define HH 12
#define DK 64
#define MTOT (BB*SS_)   // 8192

// Scratch (allocation-free rule: __device__ globals)
__device__ float g_q[(size_t)BB*HH*SS_*DK];
__device__ float g_k[(size_t)BB*HH*SS_*DK];
__device__ float g_v[(size_t)BB*HH*SS_*DK];
__device__ float g_o[(size_t)BB*HH*SS_*DK];

// ---------------------------------------------------------------------------
// helpers
// ---------------------------------------------------------------------------
__device__ __forceinline__ float to_tf32(float x) {
    uint32_t u;
    asm("cvt.rna.tf32.f32 %0, %1;" : "=r"(u) : "f"(x));
    return __uint_as_float(u);
}

__device__ __forceinline__ void mma_tf32(float* d, const float* a, float b0, float b1) {
    asm volatile(
        "mma.sync.aligned.m16n8k8.row.col.f32.tf32.tf32.f32 "
        "{%0,%1,%2,%3}, {%4,%5,%6,%7}, {%8,%9}, {%0,%1,%2,%3};"
        : "+f"(d[0]), "+f"(d[1]), "+f"(d[2]), "+f"(d[3])
        : "r"(__float_as_uint(a[0])), "r"(__float_as_uint(a[1])),
          "r"(__float_as_uint(a[2])), "r"(__float_as_uint(a[3])),
          "r"(__float_as_uint(b0)),   "r"(__float_as_uint(b1)));
}

__device__ __forceinline__ float4 cvt4(float4 v) {
    v.x = to_tf32(v.x); v.y = to_tf32(v.y);
    v.z = to_tf32(v.z); v.w = to_tf32(v.w);
    return v;
}

// ===========================================================================
// Projection GEMM (tf32 mma.sync), register-prefetch pipeline, K-chunk 32,
// double smem buffer, one barrier per chunk.  (unchanged — 213 us measured)
// ===========================================================================
#define PK 32
#define PAS 36
#define PBS 136
#define PBUF (128*PAS + PK*PBS)
#define PROJ_SMEM (2 * PBUF * 4)

__device__ __forceinline__ void proj_ldg(
    float4* Ar, float4* Br,
    const float* __restrict__ A_base, const float* __restrict__ Wm,
    int m0, int n0, int k0, int t, int mode)
{
    if (mode == 0) {
        #pragma unroll
        for (int i = 0; i < 4; i++) {
            int idx = t + 256 * i;
            int row = idx >> 3, c4 = idx & 7;
            Ar[i] = *(const float4*)(A_base + (size_t)(m0 + row) * DD + k0 + c4 * 4);
        }
    } else {
        const int h = k0 >> 6;
        const int cb = k0 & 63;
        #pragma unroll
        for (int i = 0; i < 4; i++) {
            int idx = t + 256 * i;
            int row = idx >> 3, c4 = idx & 7;
            int m = m0 + row;
            int bb = m >> 12, ss = m & 4095;
            Ar[i] = *(const float4*)(A_base + (((size_t)bb * HH + h) * SS_ + ss) * DK + cb + c4 * 4);
        }
    }
    #pragma unroll
    for (int i = 0; i < 4; i++) {
        int idx = t + 256 * i;
        int k = idx >> 5, n4 = idx & 31;
        Br[i] = *(const float4*)(Wm + (size_t)(k0 + k) * DD + n0 + n4 * 4);
    }
}

__device__ __forceinline__ void proj_sts(
    float* As, float* Bs, const float4* Ar, const float4* Br, int t)
{
    #pragma unroll
    for (int i = 0; i < 4; i++) {
        int idx = t + 256 * i;
        *(float4*)&As[(idx >> 3) * PAS + (idx & 7) * 4] = cvt4(Ar[i]);
    }
    #pragma unroll
    for (int i = 0; i < 4; i++) {
        int idx = t + 256 * i;
        *(float4*)&Bs[(idx >> 5) * PBS + (idx & 31) * 4] = cvt4(Br[i]);
    }
}

__device__ __forceinline__ void proj_gemm_body(
    const float* __restrict__ A_base,
    const float* __restrict__ Wm, const float* __restrict__ bias,
    float* __restrict__ out, int mode)
{
    extern __shared__ float sm[];

    const int t    = threadIdx.x;
    const int w    = t >> 5;
    const int lane = t & 31;
    const int gid  = lane >> 2;
    const int tig  = lane & 3;
    const int wm   = w & 3;
    const int wn   = w >> 2;
    const int m0   = blockIdx.x * 128;
    const int n0   = blockIdx.y * 128;
    const int m0w  = wm * 32;
    const int n0w  = wn * 64;

    float acc[2][8][4];
    #pragma unroll
    for (int mt = 0; mt < 2; mt++)
        #pragma unroll
        for (int nt = 0; nt < 8; nt++)
            #pragma unroll
            for (int i = 0; i < 4; i++) acc[mt][nt][i] = 0.f;

    float4 Ar[4], Br[4];
    proj_ldg(Ar, Br, A_base, Wm, m0, n0, 0, t, mode);
    proj_sts(sm, sm + 128 * PAS, Ar, Br, t);
    __syncthreads();

    const int NCH = DD / PK;   // 24
    for (int c = 0; c < NCH; c++) {
        const int cur = c & 1;
        float* As = sm + cur * PBUF;
        float* Bs = As + 128 * PAS;

        if (c + 1 < NCH)
            proj_ldg(Ar, Br, A_base, Wm, m0, n0, (c + 1) * PK, t, mode);

        #pragma unroll
        for (int k = 0; k < PK / 8; k++) {
            float af[2][4];
            #pragma unroll
            for (int mt = 0; mt < 2; mt++) {
                int r = m0w + mt * 16;
                af[mt][0] = As[(r + gid)     * PAS + k * 8 + tig];
                af[mt][1] = As[(r + gid + 8) * PAS + k * 8 + tig];
                af[mt][2] = As[(r + gid)     * PAS + k * 8 + tig + 4];
                af[mt][3] = As[(r + gid + 8) * PAS + k * 8 + tig + 4];
            }
            #pragma unroll
            for (int nt = 0; nt < 8; nt++) {
                float b0 = Bs[(k * 8 + tig)     * PBS + n0w + nt * 8 + gid];
                float b1 = Bs[(k * 8 + tig + 4) * PBS + n0w + nt * 8 + gid];
                mma_tf32(acc[0][nt], af[0], b0, b1);
                mma_tf32(acc[1][nt], af[1], b0, b1);
            }
        }

        if (c + 1 < NCH) {
            float* As2 = sm + (cur ^ 1) * PBUF;
            proj_sts(As2, As2 + 128 * PAS, Ar, Br, t);
        }
        __syncthreads();
    }

    #pragma unroll
    for (int mt = 0; mt < 2; mt++) {
        int mrow = m0 + m0w + mt * 16 + gid;
        #pragma unroll
        for (int nt = 0; nt < 8; nt++) {
            int n = n0 + n0w + nt * 8 + tig * 2;
            float b0 = bias[n], b1 = bias[n + 1];
            if (mode == 0) {
                int h = n >> 6, cc = n & 63;
                int bb0 = mrow >> 12, ss0 = mrow & 4095;
                int m8 = mrow + 8;
                int bb1 = m8 >> 12, ss1 = m8 & 4095;
                *(float2*)(out + (((size_t)bb0 * HH + h) * SS_ + ss0) * DK + cc) =
                    make_float2(acc[mt][nt][0] + b0, acc[mt][nt][1] + b1);
                *(float2*)(out + (((size_t)bb1 * HH + h) * SS_ + ss1) * DK + cc) =
                    make_float2(acc[mt][nt][2] + b0, acc[mt][nt][3] + b1);
            } else {
                *(float2*)(out + (size_t)mrow * DD + n) =
                    make_float2(acc[mt][nt][0] + b0, acc[mt][nt][1] + b1);
                *(float2*)(out + (size_t)(mrow + 8) * DD + n) =
                    make_float2(acc[mt][nt][2] + b0, acc[mt][nt][3] + b1);
            }
        }
    }
}

__global__ __launch_bounds__(256, 2) void gemm_qkv_mma(
    const float* __restrict__ X,
    const float* __restrict__ wq, const float* __restrict__ bq,
    const float* __restrict__ wk, const float* __restrict__ bk,
    const float* __restrict__ wv, const float* __restrict__ bv)
{
    const float* Wm; const float* bias; float* out;
    if (blockIdx.z == 0)      { Wm = wq; bias = bq; out = g_q; }
    else if (blockIdx.z == 1) { Wm = wk; bias = bk; out = g_k; }
    else                      { Wm = wv; bias = bv; out = g_v; }
    proj_gemm_body(X, Wm, bias, out, 0);
}

__global__ __launch_bounds__(256, 2) void gemm_out_mma(
    const float* __restrict__ wo, const float* __restrict__ bo,
    float* __restrict__ Y)
{
    proj_gemm_body(g_o, wo, bo, Y, 1);
}

// ---------------------------------------------------------------------------
// Flash attention, mma.sync tf32 (m16n8k8), wide warp tiles (R14 shape):
// CTA = 128 threads / 4 warps; warp w owns 32 q rows (2 m-tiles of 16).
// NEW: Q fragments cached in registers for the whole kernel (qf[2][8][4]),
// Q smem slab removed -> LDS/mma drops 1.25 -> 1.0, smem 106.5 -> 71.7 KB.
// K/V double-buffered, one barrier/iter; next-tile prefetch split (K after
// softmax chunk 2, V after chunk 5) to bound register pressure.
// smem: K 2x[64][68], V 2x[64][72]   (71680 B, 2 CTA/SM)
// ---------------------------------------------------------------------------
#define TKV 64
#define KS_STR 68
#define VS_STR 72
#define KVBUF (TKV*KS_STR + TKV*VS_STR)
#define ATT_SMEM (2 * KVBUF * 4)   // 71680 B

__device__ __forceinline__ void attn_ldg_k(
    float4* Kr, const float* __restrict__ Kg, int kv0, int t)
{
    #pragma unroll
    for (int i = 0; i < 8; i++) {
        int f = t + 128 * i;
        int row = f >> 4, c4 = f & 15;
        Kr[i] = *(const float4*)(Kg + (size_t)(kv0 + row) * DK + c4 * 4);
    }
}

__device__ __forceinline__ void attn_ldg_v(
    float4* Vr, const float* __restrict__ Vg, int kv0, int t)
{
    #pragma unroll
    for (int i = 0; i < 8; i++) {
        int f = t + 128 * i;
        int row = f >> 4, c4 = f & 15;
        Vr[i] = *(const float4*)(Vg + (size_t)(kv0 + row) * DK + c4 * 4);
    }
}

__device__ __forceinline__ void attn_sts(
    float* Ks, float* Vs, const float4* Kr, const float4* Vr, int t)
{
    #pragma unroll
    for (int i = 0; i < 8; i++) {
        int f = t + 128 * i;
        *(float4*)&Ks[(f >> 4) * KS_STR + (f & 15) * 4] = cvt4(Kr[i]);
    }
    #pragma unroll
    for (int i = 0; i < 8; i++) {
        int f = t + 128 * i;
        *(float4*)&Vs[(f >> 4) * VS_STR + (f & 15) * 4] = cvt4(Vr[i]);
    }
}

__global__ __launch_bounds__(128, 2) void attn_mma()
{
    extern __shared__ float sm[];
    float* KV0 = sm;                       // buffer 0: K[64][68] V[64][72]
    float* KV1 = KV0 + KVBUF;              // buffer 1

    const int t    = threadIdx.x;
    const int w    = t >> 5;               // 0..3
    const int lane = t & 31;
    const int gid  = lane >> 2;
    const int tig  = lane & 3;

    const int q0 = blockIdx.x * 128;
    const int bh = blockIdx.y;

    const float* Qg = g_q + (size_t)bh * SS_ * DK;
    const float* Kg = g_k + (size_t)bh * SS_ * DK;
    const float* Vg = g_v + (size_t)bh * SS_ * DK;
    float*       Og = g_o + (size_t)bh * SS_ * DK;

    // shuffle source lanes for P redistribution (within quad)
    const int s0 = (lane & ~3) | (tig >> 1);
    const int s2 = s0 + 2;
    const bool odd = (tig & 1);

    const int qrow = w * 32;   // warp's q-row base within tile (2 m-tiles)

    // ---- Q fragments in registers for the WHOLE kernel (scaled, tf32) ----
    float qf[2][8][4];
    #pragma unroll
    for (int mt = 0; mt < 2; mt++) {
        const float* r0 = Qg + (size_t)(q0 + qrow + mt * 16 + gid) * DK;
        const float* r8 = r0 + 8 * DK;
        #pragma unroll
        for (int k = 0; k < 8; k++) {
            qf[mt][k][0] = to_tf32(r0[k * 8 + tig]     * 0.125f);
            qf[mt][k][1] = to_tf32(r8[k * 8 + tig]     * 0.125f);
            qf[mt][k][2] = to_tf32(r0[k * 8 + tig + 4] * 0.125f);
            qf[mt][k][3] = to_tf32(r8[k * 8 + tig + 4] * 0.125f);
        }
    }

    // ---- stage K/V tile 0 into buffer 0 ----
    float4 Kr[8], Vr[8];
    attn_ldg_k(Kr, Kg, 0, t);
    attn_ldg_v(Vr, Vg, 0, t);
    attn_sts(KV0, KV0 + TKV * KS_STR, Kr, Vr, t);
    __syncthreads();

    float oacc[2][8][4];
    #pragma unroll
    for (int mt = 0; mt < 2; mt++)
        #pragma unroll
        for (int n = 0; n < 8; n++)
            #pragma unroll
            for (int i = 0; i < 4; i++) oacc[mt][n][i] = 0.f;
    float ls[2][2] = {{0.f, 0.f}, {0.f, 0.f}};

    const int NIT = SS_ / TKV;   // 64
    for (int it = 0; it < NIT; it++) {
        float* Ks = (it & 1) ? KV1 : KV0;
        float* Vs = Ks + TKV * KS_STR;
        float* KsN = (it & 1) ? KV0 : KV1;

        // ---- S = Q K^T  (2 m-tiles share every K b-fragment) ----
        float sacc[2][8][4];
        #pragma unroll
        for (int mt = 0; mt < 2; mt++)
            #pragma unroll
            for (int n = 0; n < 8; n++)
                #pragma unroll
                for (int i = 0; i < 4; i++) sacc[mt][n][i] = 0.f;

        #pragma unroll
        for (int k = 0; k < 8; k++) {
            #pragma unroll
            for (int nt = 0; nt < 8; nt++) {
                float b0 = Ks[(nt * 8 + gid) * KS_STR + k * 8 + tig];
                float b1 = Ks[(nt * 8 + gid) * KS_STR + k * 8 + tig + 4];
                mma_tf32(sacc[0][nt], qf[0][k], b0, b1);
                mma_tf32(sacc[1][nt], qf[1][k], b0, b1);
            }
        }

        // ---- softmax + PV, interleaved; P via quad shuffles;
        //      next-tile prefetch split across the kc loop ----
        #pragma unroll
        for (int kc = 0; kc < 8; kc++) {
            if (kc == 3 && it + 1 < NIT)
                attn_ldg_k(Kr, Kg, (it + 1) * TKV, t);
            if (kc == 6 && it + 1 < NIT)
                attn_ldg_v(Vr, Vg, (it + 1) * TKV, t);

            float af[2][4];
            #pragma unroll
            for (int mt = 0; mt < 2; mt++) {
                float p0 = __expf(sacc[mt][kc][0]);
                float p1 = __expf(sacc[mt][kc][1]);
                float p2 = __expf(sacc[mt][kc][2]);
                float p3 = __expf(sacc[mt][kc][3]);
                ls[mt][0] += p0 + p1;
                ls[mt][1] += p2 + p3;

                float v00 = __shfl_sync(0xffffffffu, p0, s0);
                float v01 = __shfl_sync(0xffffffffu, p1, s0);
                float v10 = __shfl_sync(0xffffffffu, p2, s0);
                float v11 = __shfl_sync(0xffffffffu, p3, s0);
                float v20 = __shfl_sync(0xffffffffu, p0, s2);
                float v21 = __shfl_sync(0xffffffffu, p1, s2);
                float v30 = __shfl_sync(0xffffffffu, p2, s2);
                float v31 = __shfl_sync(0xffffffffu, p3, s2);

                af[mt][0] = to_tf32(odd ? v01 : v00);
                af[mt][1] = to_tf32(odd ? v11 : v10);
                af[mt][2] = to_tf32(odd ? v21 : v20);
                af[mt][3] = to_tf32(odd ? v31 : v30);
            }

            #pragma unroll
            for (int nt = 0; nt < 8; nt++) {
                float b0 = Vs[(kc * 8 + tig)     * VS_STR + nt * 8 + gid];
                float b1 = Vs[(kc * 8 + tig + 4) * VS_STR + nt * 8 + gid];
                mma_tf32(oacc[0][nt], af[0], b0, b1);
                mma_tf32(oacc[1][nt], af[1], b0, b1);
            }
        }

        // ---- store next tile into the other buffer, one barrier ----
        if (it + 1 < NIT)
            attn_sts(KsN, KsN + TKV * KS_STR, Kr, Vr, t);
        __syncthreads();
    }

    // ---- finalize ----
    #pragma unroll
    for (int mt = 0; mt < 2; mt++) {
        float l0 = ls[mt][0], l1 = ls[mt][1];
        l0 += __shfl_xor_sync(0xffffffffu, l0, 1);
        l0 += __shfl_xor_sync(0xffffffffu, l0, 2);
        l1 += __shfl_xor_sync(0xffffffffu, l1, 1);
        l1 += __shfl_xor_sync(0xffffffffu, l1, 2);
        const float inv0 = 1.f / l0;
        const float inv1 = 1.f / l1;

        const int row0 = q0 + qrow + mt * 16 + gid;
        #pragma unroll
        for (int nt = 0; nt < 8; nt++) {
            *(float2*)(Og + (size_t)row0 * DK + nt * 8 + tig * 2) =
                make_float2(oacc[mt][nt][0] * inv0, oacc[mt][nt][1] * inv0);
            *(float2*)(Og + (size_t)(row0 + 8) * DK + nt * 8 + tig * 2) =
                make_float2(oacc[mt][nt][2] * inv1, oacc[mt][nt][3] * inv1);
        }
    }
}

// ---------------------------------------------------------------------------
extern "C" void kernel_launch(void* const* d_in, const int* in_sizes, int n_in,
                              void* d_out, int out_size)
{
    (void)in_sizes; (void)n_in; (void)out_size;
    const float* x  = (const float*)d_in[0];
    const float* wq = (const float*)d_in[1];
    const float* bq = (const float*)d_in[2];
    const float* wk = (const float*)d_in[3];
    const float* bk = (const float*)d_in[4];
    const float* wv = (const float*)d_in[5];
    const float* bv = (const float*)d_in[6];
    const float* wo = (const float*)d_in[7];
    const float* bo = (const float*)d_in[8];
    float* y = (float*)d_out;

    cudaFuncSetAttribute(attn_mma,     cudaFuncAttributeMaxDynamicSharedMemorySize, ATT_SMEM);
    cudaFuncSetAttribute(gemm_qkv_mma, cudaFuncAttributeMaxDynamicSharedMemorySize, PROJ_SMEM);
    cudaFuncSetAttribute(gemm_out_mma, cudaFuncAttributeMaxDynamicSharedMemorySize, PROJ_SMEM);

    dim3 gq(MTOT / 128, DD / 128, 3);
    gemm_qkv_mma<<<gq, 256, PROJ_SMEM>>>(x, wq, bq, wk, bk, wv, bv);

    dim3 ga(SS_ / 128, BB * HH);
    attn_mma<<<ga, 128, ATT_SMEM>>>();

    dim3 go(MTOT / 128, DD / 128);
    gemm_out_mma<<<go, 256, PROJ_SMEM>>>(wo, bo, y);
}

// round 17
// speedup vs baseline: 2.5836x; 1.7031x over previous
#include <cuda_runtime.h>
#include <cuda_fp16.h>
#include <cstdint>
#include <math.h>

#define BB 2
#define SS_ 4096
#define DD 768
#define HH 12
#define DK 64
#define MTOT (BB*SS_)   // 8192

// Scratch (allocation-free rule: __device__ globals)
__device__ float g_q[(size_t)BB*HH*SS_*DK];
__device__ float g_k[(size_t)BB*HH*SS_*DK];
__device__ float g_v[(size_t)BB*HH*SS_*DK];   // stored TRANSPOSED: [B,H,DK,S]
__device__ float g_o[(size_t)BB*HH*SS_*DK];

// ---------------------------------------------------------------------------
// helpers
// ---------------------------------------------------------------------------
__device__ __forceinline__ uint32_t h2(float a, float b) {
    __half2 v = __floats2half2_rn(a, b);
    return *reinterpret_cast<uint32_t*>(&v);
}

__device__ __forceinline__ void mma_fp16(float* d, const uint32_t* a,
                                         uint32_t b0, uint32_t b1) {
    asm volatile(
        "mma.sync.aligned.m16n8k16.row.col.f32.f16.f16.f32 "
        "{%0,%1,%2,%3}, {%4,%5,%6,%7}, {%8,%9}, {%0,%1,%2,%3};"
        : "+f"(d[0]), "+f"(d[1]), "+f"(d[2]), "+f"(d[3])
        : "r"(a[0]), "r"(a[1]), "r"(a[2]), "r"(a[3]), "r"(b0), "r"(b1));
}

// ===========================================================================
// Projection GEMM, fp16 m16n8k16.  CTA 128x128, K-chunk 32 (2 k16 steps),
// double smem buffer, register-prefetch, one barrier per chunk.
// As  [128 rows][72 halves] (word-stride 36 -> a-frag bank 4*gid+tig, unique)
// Bsn [128 n][40 halves]    (word-stride 20 -> b-frag banks unique)
// ===========================================================================
#define PK 32
#define AS_H 72
#define BS_H 40
#define PBUF_H (128*AS_H + 128*BS_H)          // halves per buffer = 14336
#define PROJ_SMEM (2 * PBUF_H * 2)            // 57344 B

// MODE: 0 = QKV (A = X row-major; scatter to [B,H,S,dk]; vt: V transposed)
//       1 = OUT (A = g_o gathered; C -> Y row-major [M,768])
__device__ __forceinline__ void proj_ldg(
    float4* Ar, float* br,
    const float* __restrict__ A_base, const float* __restrict__ Wm,
    int m0, int n0, int k0, int t, int mode)
{
    if (mode == 0) {
        #pragma unroll
        for (int i = 0; i < 4; i++) {
            int idx = t + 256 * i;
            int row = idx >> 3, c4 = idx & 7;
            Ar[i] = *(const float4*)(A_base + (size_t)(m0 + row) * DD + k0 + c4 * 4);
        }
    } else {
        const int h = k0 >> 6;
        const int cb = k0 & 63;
        #pragma unroll
        for (int i = 0; i < 4; i++) {
            int idx = t + 256 * i;
            int row = idx >> 3, c4 = idx & 7;
            int m = m0 + row;
            int bb = m >> 12, ss = m & 4095;
            Ar[i] = *(const float4*)(A_base + (((size_t)bb * HH + h) * SS_ + ss) * DK + cb + c4 * 4);
        }
    }
    // B: gather 4 k-values per (n, k-quad) task; lanes consecutive in n (coalesced)
    #pragma unroll
    for (int i = 0; i < 4; i++) {
        int idx = t + 256 * i;
        int n = idx & 127, k4 = idx >> 7;
        #pragma unroll
        for (int j = 0; j < 4; j++)
            br[i * 4 + j] = Wm[(size_t)(k0 + k4 * 4 + j) * DD + n0 + n];
    }
}

__device__ __forceinline__ void proj_sts(
    __half* As, __half* Bs, const float4* Ar, const float* br, int t)
{
    #pragma unroll
    for (int i = 0; i < 4; i++) {
        int idx = t + 256 * i;
        int row = idx >> 3, c4 = idx & 7;
        uint2 v = make_uint2(h2(Ar[i].x, Ar[i].y), h2(Ar[i].z, Ar[i].w));
        *(uint2*)&As[row * AS_H + c4 * 4] = v;
    }
    #pragma unroll
    for (int i = 0; i < 4; i++) {
        int idx = t + 256 * i;
        int n = idx & 127, k4 = idx >> 7;
        uint2 v = make_uint2(h2(br[i*4+0], br[i*4+1]), h2(br[i*4+2], br[i*4+3]));
        *(uint2*)&Bs[n * BS_H + k4 * 4] = v;
    }
}

__device__ __forceinline__ void proj_gemm_body(
    const float* __restrict__ A_base,
    const float* __restrict__ Wm, const float* __restrict__ bias,
    float* __restrict__ out, int mode, int vt)
{
    extern __shared__ __half smh[];

    const int t    = threadIdx.x;
    const int w    = t >> 5;
    const int lane = t & 31;
    const int gid  = lane >> 2;
    const int tig  = lane & 3;
    const int wm   = w & 3;
    const int wn   = w >> 2;
    const int m0   = blockIdx.x * 128;
    const int n0   = blockIdx.y * 128;
    const int m0w  = wm * 32;
    const int n0w  = wn * 64;

    float acc[2][8][4];
    #pragma unroll
    for (int mt = 0; mt < 2; mt++)
        #pragma unroll
        for (int nt = 0; nt < 8; nt++)
            #pragma unroll
            for (int i = 0; i < 4; i++) acc[mt][nt][i] = 0.f;

    float4 Ar[4]; float br[16];
    proj_ldg(Ar, br, A_base, Wm, m0, n0, 0, t, mode);
    proj_sts(smh, smh + 128 * AS_H, Ar, br, t);
    __syncthreads();

    const int NCH = DD / PK;   // 24
    for (int c = 0; c < NCH; c++) {
        const int cur = c & 1;
        __half* As = smh + cur * PBUF_H;
        __half* Bs = As + 128 * AS_H;

        if (c + 1 < NCH)
            proj_ldg(Ar, br, A_base, Wm, m0, n0, (c + 1) * PK, t, mode);

        #pragma unroll
        for (int kcc = 0; kcc < 2; kcc++) {
            uint32_t af[2][4];
            #pragma unroll
            for (int mt = 0; mt < 2; mt++) {
                int base = (m0w + mt * 16 + gid) * AS_H + kcc * 16 + 2 * tig;
                af[mt][0] = *(uint32_t*)&As[base];
                af[mt][1] = *(uint32_t*)&As[base + 8 * AS_H];
                af[mt][2] = *(uint32_t*)&As[base + 8];
                af[mt][3] = *(uint32_t*)&As[base + 8 * AS_H + 8];
            }
            #pragma unroll
            for (int nt = 0; nt < 8; nt++) {
                int bb_ = (n0w + nt * 8 + gid) * BS_H + kcc * 16 + 2 * tig;
                uint32_t b0 = *(uint32_t*)&Bs[bb_];
                uint32_t b1 = *(uint32_t*)&Bs[bb_ + 8];
                mma_fp16(acc[0][nt], af[0], b0, b1);
                mma_fp16(acc[1][nt], af[1], b0, b1);
            }
        }

        if (c + 1 < NCH) {
            __half* As2 = smh + (cur ^ 1) * PBUF_H;
            proj_sts(As2, As2 + 128 * AS_H, Ar, br, t);
        }
        __syncthreads();
    }

    // ---- epilogue ----
    #pragma unroll
    for (int mt = 0; mt < 2; mt++) {
        int mrow = m0 + m0w + mt * 16 + gid;
        #pragma unroll
        for (int nt = 0; nt < 8; nt++) {
            int n = n0 + n0w + nt * 8 + tig * 2;
            float b0 = bias[n], b1 = bias[n + 1];
            if (mode == 0) {
                int h = n >> 6, cc = n & 63;
                int bb0 = mrow >> 12, ss0 = mrow & 4095;
                int m8 = mrow + 8;
                int bb1 = m8 >> 12, ss1 = m8 & 4095;
                if (vt) {   // V: transposed store [B,H,DK,S]
                    size_t base0 = ((size_t)bb0 * HH + h) * DK;
                    size_t base1 = ((size_t)bb1 * HH + h) * DK;
                    out[(base0 + cc)     * SS_ + ss0] = acc[mt][nt][0] + b0;
                    out[(base0 + cc + 1) * SS_ + ss0] = acc[mt][nt][1] + b1;
                    out[(base1 + cc)     * SS_ + ss1] = acc[mt][nt][2] + b0;
                    out[(base1 + cc + 1) * SS_ + ss1] = acc[mt][nt][3] + b1;
                } else {
                    *(float2*)(out + (((size_t)bb0 * HH + h) * SS_ + ss0) * DK + cc) =
                        make_float2(acc[mt][nt][0] + b0, acc[mt][nt][1] + b1);
                    *(float2*)(out + (((size_t)bb1 * HH + h) * SS_ + ss1) * DK + cc) =
                        make_float2(acc[mt][nt][2] + b0, acc[mt][nt][3] + b1);
                }
            } else {
                *(float2*)(out + (size_t)mrow * DD + n) =
                    make_float2(acc[mt][nt][0] + b0, acc[mt][nt][1] + b1);
                *(float2*)(out + (size_t)(mrow + 8) * DD + n) =
                    make_float2(acc[mt][nt][2] + b0, acc[mt][nt][3] + b1);
            }
        }
    }
}

__global__ __launch_bounds__(256, 2) void gemm_qkv_mma(
    const float* __restrict__ X,
    const float* __restrict__ wq, const float* __restrict__ bq,
    const float* __restrict__ wk, const float* __restrict__ bk,
    const float* __restrict__ wv, const float* __restrict__ bv)
{
    const float* Wm; const float* bias; float* out;
    if (blockIdx.z == 0)      { Wm = wq; bias = bq; out = g_q; }
    else if (blockIdx.z == 1) { Wm = wk; bias = bk; out = g_k; }
    else                      { Wm = wv; bias = bv; out = g_v; }
    proj_gemm_body(X, Wm, bias, out, 0, blockIdx.z == 2 ? 1 : 0);
}

__global__ __launch_bounds__(256, 2) void gemm_out_mma(
    const float* __restrict__ wo, const float* __restrict__ bo,
    float* __restrict__ Y)
{
    proj_gemm_body(g_o, wo, bo, Y, 1, 0);
}

// ---------------------------------------------------------------------------
// Flash attention, fp16 mma m16n8k16, wide warp tiles.
// CTA = 128 threads / 4 warps; warp w owns 32 q rows (2 m-tiles of 16).
// - Q fragments in registers (packed fp16, scaled by 1/8)
// - K smem [kv][d] half, stride 72; V smem TRANSPOSED [d][kv] half, stride 72
//   (g_v already [B,H,DK,S]); b-frag = one aligned half2 LDS each.
// - PV A-fragments come DIRECTLY from exp'd QK C-fragments (no shuffles!)
// - K/V double-buffered; staging split across PV kc-steps; one barrier/iter
// smem: 2 x (K 64x72 + Vt 64x72) halves = 36864 B -> 2 CTA/SM
// ---------------------------------------------------------------------------
#define TKV 64
#define KS_H 72
#define KVBUF_H (2 * 64 * KS_H)               // halves per buffer (K + Vt)
#define ATT_SMEM (2 * KVBUF_H * 2)            // 36864 B

// load half-tile (32 rows) of K: hs=0 rows 0-31, hs=1 rows 32-63
__device__ __forceinline__ void att_ldg_k(
    float4* r, const float* __restrict__ Kg, int kv0, int t, int hs)
{
    #pragma unroll
    for (int i = 0; i < 4; i++) {
        int f = t + 128 * (i + 4 * hs);
        int row = f >> 4, c4 = f & 15;
        r[i] = *(const float4*)(Kg + (size_t)(kv0 + row) * DK + c4 * 4);
    }
}
// load half-tile of Vt (rows = d)
__device__ __forceinline__ void att_ldg_v(
    float4* r, const float* __restrict__ Vtg, int kv0, int t, int hs)
{
    #pragma unroll
    for (int i = 0; i < 4; i++) {
        int f = t + 128 * (i + 4 * hs);
        int d = f >> 4, c4 = f & 15;
        r[i] = *(const float4*)(Vtg + (size_t)d * SS_ + kv0 + c4 * 4);
    }
}
__device__ __forceinline__ void att_sts(
    __half* dst, const float4* r, int t, int hs)
{
    #pragma unroll
    for (int i = 0; i < 4; i++) {
        int f = t + 128 * (i + 4 * hs);
        int row = f >> 4, c4 = f & 15;
        uint2 v = make_uint2(h2(r[i].x, r[i].y), h2(r[i].z, r[i].w));
        *(uint2*)&dst[row * KS_H + c4 * 4] = v;
    }
}

__global__ __launch_bounds__(128, 2) void attn_mma()
{
    extern __shared__ __half smh[];
    __half* B0 = smh;                 // buffer 0: K[64][72] then Vt[64][72]
    __half* B1 = smh + KVBUF_H;       // buffer 1

    const int t    = threadIdx.x;
    const int w    = t >> 5;
    const int lane = t & 31;
    const int gid  = lane >> 2;
    const int tig  = lane & 3;

    const int q0 = blockIdx.x * 128;
    const int bh = blockIdx.y;

    const float* Qg  = g_q + (size_t)bh * SS_ * DK;
    const float* Kg  = g_k + (size_t)bh * SS_ * DK;
    const float* Vtg = g_v + (size_t)bh * DK * SS_;   // [DK][S]
    float*       Og  = g_o + (size_t)bh * SS_ * DK;

    const int qrow = w * 32;

    // ---- Q fragments in registers (packed fp16, scaled by 1/8) ----
    uint32_t qf[2][4][4];
    #pragma unroll
    for (int mt = 0; mt < 2; mt++) {
        const float* r0 = Qg + (size_t)(q0 + qrow + mt * 16 + gid) * DK;
        const float* r8 = r0 + 8 * DK;
        #pragma unroll
        for (int kc = 0; kc < 4; kc++) {
            int d0 = 16 * kc + 2 * tig;
            qf[mt][kc][0] = h2(r0[d0]     * 0.125f, r0[d0 + 1] * 0.125f);
            qf[mt][kc][1] = h2(r8[d0]     * 0.125f, r8[d0 + 1] * 0.125f);
            qf[mt][kc][2] = h2(r0[d0 + 8] * 0.125f, r0[d0 + 9] * 0.125f);
            qf[mt][kc][3] = h2(r8[d0 + 8] * 0.125f, r8[d0 + 9] * 0.125f);
        }
    }

    // ---- stage tile 0 into buffer 0 ----
    {
        float4 ra[4], rb[4];
        att_ldg_k(ra, Kg, 0, t, 0);
        att_ldg_k(rb, Kg, 0, t, 1);
        att_sts(B0, ra, t, 0);
        att_sts(B0, rb, t, 1);
        att_ldg_v(ra, Vtg, 0, t, 0);
        att_ldg_v(rb, Vtg, 0, t, 1);
        att_sts(B0 + 64 * KS_H, ra, t, 0);
        att_sts(B0 + 64 * KS_H, rb, t, 1);
    }
    __syncthreads();

    float oacc[2][8][4];
    #pragma unroll
    for (int mt = 0; mt < 2; mt++)
        #pragma unroll
        for (int n = 0; n < 8; n++)
            #pragma unroll
            for (int i = 0; i < 4; i++) oacc[mt][n][i] = 0.f;
    float ls[2][2] = {{0.f, 0.f}, {0.f, 0.f}};

    float4 krA[4], krB[4];

    const int NIT = SS_ / TKV;   // 64
    for (int it = 0; it < NIT; it++) {
        __half* Ks  = (it & 1) ? B1 : B0;
        __half* Vts = Ks + 64 * KS_H;
        __half* KsN = (it & 1) ? B0 : B1;
        __half* VtsN = KsN + 64 * KS_H;
        const bool more = (it + 1 < NIT);
        const int nkv = (it + 1) * TKV;

        // ---- S = Q K^T : 4 k16 chunks ----
        float sacc[2][8][4];
        #pragma unroll
        for (int mt = 0; mt < 2; mt++)
            #pragma unroll
            for (int n = 0; n < 8; n++)
                #pragma unroll
                for (int i = 0; i < 4; i++) sacc[mt][n][i] = 0.f;

        #pragma unroll
        for (int kc = 0; kc < 4; kc++) {
            #pragma unroll
            for (int nt = 0; nt < 8; nt++) {
                int base = (nt * 8 + gid) * KS_H + 16 * kc + 2 * tig;
                uint32_t b0 = *(uint32_t*)&Ks[base];
                uint32_t b1 = *(uint32_t*)&Ks[base + 8];
                mma_fp16(sacc[0][nt], qf[0][kc], b0, b1);
                mma_fp16(sacc[1][nt], qf[1][kc], b0, b1);
            }
        }

        // ---- softmax + PV fused per k16 chunk; staging interleaved ----
        #pragma unroll
        for (int kc = 0; kc < 4; kc++) {
            if (more) {
                if (kc == 0)      att_ldg_k(krA, Kg, nkv, t, 0);
                else if (kc == 1) { att_ldg_k(krB, Kg, nkv, t, 1); att_sts(KsN, krA, t, 0); }
                else if (kc == 2) { att_ldg_v(krA, Vtg, nkv, t, 0); att_sts(KsN, krB, t, 1); }
                else              { att_ldg_v(krB, Vtg, nkv, t, 1); att_sts(VtsN, krA, t, 0); }
            }

            uint32_t af[2][4];
            #pragma unroll
            for (int mt = 0; mt < 2; mt++) {
                float p0 = __expf(sacc[mt][2*kc][0]);
                float p1 = __expf(sacc[mt][2*kc][1]);
                float p2 = __expf(sacc[mt][2*kc][2]);
                float p3 = __expf(sacc[mt][2*kc][3]);
                float p4 = __expf(sacc[mt][2*kc+1][0]);
                float p5 = __expf(sacc[mt][2*kc+1][1]);
                float p6 = __expf(sacc[mt][2*kc+1][2]);
                float p7 = __expf(sacc[mt][2*kc+1][3]);
                ls[mt][0] += (p0 + p1) + (p4 + p5);
                ls[mt][1] += (p2 + p3) + (p6 + p7);
                af[mt][0] = h2(p0, p1);
                af[mt][1] = h2(p2, p3);
                af[mt][2] = h2(p4, p5);
                af[mt][3] = h2(p6, p7);
            }

            #pragma unroll
            for (int nt = 0; nt < 8; nt++) {
                int base = (nt * 8 + gid) * KS_H + 16 * kc + 2 * tig;
                uint32_t b0 = *(uint32_t*)&Vts[base];
                uint32_t b1 = *(uint32_t*)&Vts[base + 8];
                mma_fp16(oacc[0][nt], af[0], b0, b1);
                mma_fp16(oacc[1][nt], af[1], b0, b1);
            }
        }

        if (more)
            att_sts(VtsN, krB, t, 1);
        __syncthreads();
    }

    // ---- finalize ----
    #pragma unroll
    for (int mt = 0; mt < 2; mt++) {
        float l0 = ls[mt][0], l1 = ls[mt][1];
        l0 += __shfl_xor_sync(0xffffffffu, l0, 1);
        l0 += __shfl_xor_sync(0xffffffffu, l0, 2);
        l1 += __shfl_xor_sync(0xffffffffu, l1, 1);
        l1 += __shfl_xor_sync(0xffffffffu, l1, 2);
        const float inv0 = 1.f / l0;
        const float inv1 = 1.f / l1;

        const int row0 = q0 + qrow + mt * 16 + gid;
        #pragma unroll
        for (int nt = 0; nt < 8; nt++) {
            *(float2*)(Og + (size_t)row0 * DK + nt * 8 + tig * 2) =
                make_float2(oacc[mt][nt][0] * inv0, oacc[mt][nt][1] * inv0);
            *(float2*)(Og + (size_t)(row0 + 8) * DK + nt * 8 + tig * 2) =
                make_float2(oacc[mt][nt][2] * inv1, oacc[mt][nt][3] * inv1);
        }
    }
}

// ---------------------------------------------------------------------------
extern "C" void kernel_launch(void* const* d_in, const int* in_sizes, int n_in,
                              void* d_out, int out_size)
{
    (void)in_sizes; (void)n_in; (void)out_size;
    const float* x  = (const float*)d_in[0];
    const float* wq = (const float*)d_in[1];
    const float* bq = (const float*)d_in[2];
    const float* wk = (const float*)d_in[3];
    const float* bk = (const float*)d_in[4];
    const float* wv = (const float*)d_in[5];
    const float* bv = (const float*)d_in[6];
    const float* wo = (const float*)d_in[7];
    const float* bo = (const float*)d_in[8];
    float* y = (float*)d_out;

    cudaFuncSetAttribute(attn_mma,     cudaFuncAttributeMaxDynamicSharedMemorySize, ATT_SMEM);
    cudaFuncSetAttribute(gemm_qkv_mma, cudaFuncAttributeMaxDynamicSharedMemorySize, PROJ_SMEM);
    cudaFuncSetAttribute(gemm_out_mma, cudaFuncAttributeMaxDynamicSharedMemorySize, PROJ_SMEM);

    dim3 gq(MTOT / 128, DD / 128, 3);
    gemm_qkv_mma<<<gq, 256, PROJ_SMEM>>>(x, wq, bq, wk, bk, wv, bv);

    dim3 ga(SS_ / 128, BB * HH);
    attn_mma<<<ga, 128, ATT_SMEM>>>();

    dim3 go(MTOT / 128, DD / 128);
    gemm_out_mma<<<go, 256, PROJ_SMEM>>>(wo, bo, y);
}